// round 17
// baseline (speedup 1.0000x reference)
#include <cuda_runtime.h>
#include <cuda_bf16.h>
#include <cstdint>

// ---------------- constants ----------------
#define NB      8
#define CI      256
#define HW      1600
#define DM      128
#define NHEAD   8
#define DH      16
#define NROWS   (NB*HW)        // 12800
#define NCLOUD  32768

// ---------------- device scratch ----------------
__device__ float g_tok [NROWS*DM];     // l2-normalized image tokens
__device__ float g_attn[NROWS*DM];     // attention output
__device__ float g_m0  [NB*DM];        // per (b, dim) sum of normalized tokens
__device__ float g_imgacc[NB*CI];
__device__ float g_seg  [NB*DM];
__device__ float g_cnt  [NB];
// preconverted weight planes (hi/lo bf16)
__device__ __nv_bfloat16 g_w1h[CI*DM];
__device__ __nv_bfloat16 g_w1l[CI*DM];
__device__ __nv_bfloat16 g_w2h[DM*CI];
__device__ __nv_bfloat16 g_w2l[DM*CI];

typedef unsigned long long u64;

// ---------------- packed f32x2 helpers ----------------
__device__ __forceinline__ u64 fma2(u64 a, u64 b, u64 c){
  u64 d; asm("fma.rn.f32x2 %0, %1, %2, %3;" : "=l"(d) : "l"(a), "l"(b), "l"(c)); return d;
}
__device__ __forceinline__ u64 mul2(u64 a, u64 b){
  u64 d; asm("mul.rn.f32x2 %0, %1, %2;" : "=l"(d) : "l"(a), "l"(b)); return d;
}
__device__ __forceinline__ u64 pack2(float x, float y){
  u64 d; asm("mov.b64 %0, {%1, %2};" : "=l"(d) : "f"(x), "f"(y)); return d;
}
__device__ __forceinline__ float2 unpack2(u64 u){
  float2 f; asm("mov.b64 {%0, %1}, %2;" : "=f"(f.x), "=f"(f.y) : "l"(u)); return f;
}

__device__ __forceinline__ uint32_t cvt_bf16x2(u64 p){
  float2 f = unpack2(p);
  uint32_t r;
  asm("cvt.rn.bf16x2.f32 %0, %1, %2;" : "=r"(r) : "f"(f.y), "f"(f.x));
  return r;
}
__device__ __forceinline__ uint32_t cvt_bf16x2_ff(float lo, float hi){
  uint32_t r;
  asm("cvt.rn.bf16x2.f32 %0, %1, %2;" : "=r"(r) : "f"(hi), "f"(lo));
  return r;
}
__device__ __forceinline__ uint32_t packbf(__nv_bfloat16 a, __nv_bfloat16 b){
  __nv_bfloat162 t(a, b);
  return *reinterpret_cast<uint32_t*>(&t);
}

// ---------------- mma / ldmatrix helpers ----------------
__device__ __forceinline__ void mma_bf16(float* c, const uint32_t* a, uint32_t b0, uint32_t b1){
  asm volatile("mma.sync.aligned.m16n8k16.row.col.f32.bf16.bf16.f32 "
      "{%0,%1,%2,%3}, {%4,%5,%6,%7}, {%8,%9}, {%0,%1,%2,%3};"
      : "+f"(c[0]), "+f"(c[1]), "+f"(c[2]), "+f"(c[3])
      : "r"(a[0]), "r"(a[1]), "r"(a[2]), "r"(a[3]), "r"(b0), "r"(b1));
}
__device__ __forceinline__ void ldsm4(uint32_t addr, uint32_t* r){
  asm volatile("ldmatrix.sync.aligned.m8n8.x4.shared.b16 {%0,%1,%2,%3}, [%4];"
      : "=r"(r[0]), "=r"(r[1]), "=r"(r[2]), "=r"(r[3]) : "r"(addr));
}
__device__ __forceinline__ void ldsm4t(uint32_t addr, uint32_t* r){
  asm volatile("ldmatrix.sync.aligned.m8n8.x4.trans.shared.b16 {%0,%1,%2,%3}, [%4];"
      : "=r"(r[0]), "=r"(r[1]), "=r"(r[2]), "=r"(r[3]) : "r"(addr));
}
__device__ __forceinline__ void sts64(uint32_t addr, uint32_t r0, uint32_t r1){
  asm volatile("st.shared.v2.b32 [%0], {%1,%2};" :: "r"(addr), "r"(r0), "r"(r1));
}
__device__ __forceinline__ void sts128a(uint32_t addr, uint4 v){
  asm volatile("st.shared.v4.b32 [%0], {%1,%2,%3,%4};"
      :: "r"(addr), "r"(v.x), "r"(v.y), "r"(v.z), "r"(v.w));
}

// split pair of floats to hi/lo bf16x2
__device__ __forceinline__ void split2(float x0, float x1, uint32_t& hi, uint32_t& lo){
  __nv_bfloat16 h0 = __float2bfloat16_rn(x0);
  __nv_bfloat16 h1 = __float2bfloat16_rn(x1);
  float r0 = x0 - __bfloat162float(h0);
  float r1 = x1 - __bfloat162float(h1);
  hi = packbf(h0, h1);
  lo = packbf(__float2bfloat16_rn(r0), __float2bfloat16_rn(r1));
}

// ---------------- K0: zero accumulators ----------------
__global__ void zero_kernel(){
  int i = blockIdx.x*256 + threadIdx.x;
  if (i < NB*CI) g_imgacc[i] = 0.f;
  if (i < NB*DM){ g_seg[i] = 0.f; g_m0[i] = 0.f; }
  if (i < NB)    g_cnt[i]  = 0.f;
}

// ---------------- K0b: preconvert W1/W2 into hi/lo bf16 planes ----------------
__global__ void prep_w_kernel(const float* __restrict__ W1, const float* __restrict__ W2){
  int i = blockIdx.x*256 + threadIdx.x;     // 32768 elements each
  float x = W1[i];
  __nv_bfloat16 h = __float2bfloat16_rn(x);
  g_w1h[i] = h;
  g_w1l[i] = __float2bfloat16_rn(x - __bfloat162float(h));
  float y = W2[i];
  h = __float2bfloat16_rn(y);
  g_w2h[i] = h;
  g_w2l[i] = __float2bfloat16_rn(y - __bfloat162float(h));
}

// ---------------- K1: gemm1 split-bf16 mma, preconverted W planes ------------
__global__ __launch_bounds__(256, 2) void gemm1_mma_kernel(const float* __restrict__ img,
                                                           const float* __restrict__ b1){
  __shared__ __align__(128) unsigned char sAh[2][2048];
  __shared__ __align__(128) unsigned char sAl[2][2048];
  __shared__ __align__(128) unsigned char sWh[2][4096];
  __shared__ __align__(128) unsigned char sWl[2][4096];
  __shared__ __align__(16)  float sOut[64*132];
  int tile = blockIdx.x;
  int b = tile / 25, pbase = (tile % 25) * 64;
  int tid = threadIdx.x, w = tid >> 5, lane = tid & 31;
  int gid = lane >> 2, tig = lane & 3, r7 = lane & 7;

  uint32_t ah0 = (uint32_t)__cvta_generic_to_shared(&sAh[0][0]);
  uint32_t al0 = (uint32_t)__cvta_generic_to_shared(&sAl[0][0]);
  uint32_t wh0 = (uint32_t)__cvta_generic_to_shared(&sWh[0][0]);
  uint32_t wl0 = (uint32_t)__cvta_generic_to_shared(&sWl[0][0]);

  const float* Abase = img + b*CI*HW + pbase;

  float oa[8][4];
  #pragma unroll
  for (int i=0;i<8;i++){ oa[i][0]=0.f; oa[i][1]=0.f; oa[i][2]=0.f; oa[i][3]=0.f; }

  int kkA = r7 + ((lane >> 4) & 1)*8;
  int uA  = (w & 3)*2 + ((lane >> 3) & 1);
  uint32_t aoff = (uint32_t)(kkA*128 + ((uA ^ (kkA & 7)))*16);
  int kkW = r7 + ((lane >> 3) & 1)*8;
  int nsel = (lane >> 4) & 1;
  int nbase8 = (w >> 2)*8;

  // A stage-store indices (unchanged)
  int kkSa = tid >> 4, r4 = tid & 15;
  uint32_t aSaddr = (uint32_t)(kkSa*128 + (((r4 >> 1) ^ (kkSa & 7)))*16 + (r4 & 1)*8);
  // W stage-store: 1 unit of 16B (8 bf16) per thread per plane
  int kkSw = tid >> 4, ncw = tid & 15;
  uint32_t wSaddr = (uint32_t)(kkSw*256 + ((ncw ^ (kkSw & 7)))*16);
  const __nv_bfloat16* w1hp = g_w1h + kkSw*DM + ncw*8;
  const __nv_bfloat16* w1lp = g_w1l + kkSw*DM + ncw*8;

  // prologue: stage 0 -> buffer 0
  {
    float4 va = *(const float4*)(Abase + (kkSa)*HW + r4*4);
    uint4 wh = *(const uint4*)(w1hp);
    uint4 wl = *(const uint4*)(w1lp);
    uint32_t h0,l0,h1,l1;
    split2(va.x, va.y, h0, l0); split2(va.z, va.w, h1, l1);
    sts64(ah0 + aSaddr, h0, h1);
    sts64(al0 + aSaddr, l0, l1);
    sts128a(wh0 + wSaddr, wh);
    sts128a(wl0 + wSaddr, wl);
  }

  for (int ks=0; ks<16; ks++){
    float4 va; uint4 whn, wln;
    if (ks < 15){
      va  = *(const float4*)(Abase + ((ks+1)*16 + kkSa)*HW + r4*4);
      whn = *(const uint4*)(w1hp + (ks+1)*16*DM);
      wln = *(const uint4*)(w1lp + (ks+1)*16*DM);
    }
    __syncthreads();
    if (ks < 15){
      uint32_t bo = (uint32_t)(((ks+1) & 1));
      uint32_t h0,l0,h1,l1;
      split2(va.x, va.y, h0, l0); split2(va.z, va.w, h1, l1);
      sts64(ah0 + bo*2048 + aSaddr, h0, h1);
      sts64(al0 + bo*2048 + aSaddr, l0, l1);
      sts128a(wh0 + bo*4096 + wSaddr, whn);
      sts128a(wl0 + bo*4096 + wSaddr, wln);
    }

    uint32_t cu = (uint32_t)(ks & 1);
    uint32_t ah[4], al[4];
    ldsm4t(ah0 + cu*2048 + aoff, ah);
    ldsm4t(al0 + cu*2048 + aoff, al);

    #pragma unroll
    for (int p=0; p<4; p++){
      int unit = nbase8 + 2*p + nsel;
      uint32_t waddr = cu*4096 + (uint32_t)(kkW*256 + ((unit ^ (kkW & 7)))*16);
      uint32_t wh[4], wl[4];
      ldsm4t(wh0 + waddr, wh);
      ldsm4t(wl0 + waddr, wl);
      mma_bf16(oa[2*p],   ah, wh[0], wh[1]);
      mma_bf16(oa[2*p],   ah, wl[0], wl[1]);
      mma_bf16(oa[2*p],   al, wh[0], wh[1]);
      mma_bf16(oa[2*p+1], ah, wh[2], wh[3]);
      mma_bf16(oa[2*p+1], ah, wl[2], wl[3]);
      mma_bf16(oa[2*p+1], al, wh[2], wh[3]);
    }
  }
  __syncthreads();

  {
    int r0 = (w & 3)*16 + gid;
    #pragma unroll
    for (int p=0; p<8; p++){
      int c0 = (w >> 2)*64 + p*8 + 2*tig;
      sOut[r0*132 + c0]       = oa[p][0];
      sOut[r0*132 + c0 + 1]   = oa[p][1];
      sOut[(r0+8)*132 + c0]   = oa[p][2];
      sOut[(r0+8)*132 + c0+1] = oa[p][3];
    }
  }
  __syncthreads();

  {
    int r = tid >> 2, seg = tid & 3;
    float xv[32];
    float s = 0.f;
    float* op = sOut + r*132 + seg*32;
    const float* bp = b1 + seg*32;
    #pragma unroll
    for (int j4=0; j4<8; j4++){
      float4 xb = *(float4*)(op + j4*4);
      float4 bb = *(const float4*)(bp + j4*4);
      float x0 = xb.x + bb.x, x1 = xb.y + bb.y, x2 = xb.z + bb.z, x3 = xb.w + bb.w;
      xv[4*j4]=x0; xv[4*j4+1]=x1; xv[4*j4+2]=x2; xv[4*j4+3]=x3;
      s += x0*x0 + x1*x1 + x2*x2 + x3*x3;
    }
    s += __shfl_xor_sync(0xffffffffu, s, 1);
    s += __shfl_xor_sync(0xffffffffu, s, 2);
    float inv = 1.0f / fmaxf(sqrtf(s), 1e-12f);
    float* tp = g_tok + (size_t)(tile*64 + r)*DM + seg*32;
    #pragma unroll
    for (int j4=0; j4<8; j4++){
      float4 o = make_float4(xv[4*j4]*inv, xv[4*j4+1]*inv, xv[4*j4+2]*inv, xv[4*j4+3]*inv);
      *(float4*)(tp + j4*4) = o;
      *(float4*)(op + j4*4) = o;
    }
  }
  __syncthreads();

  if (tid < 128){
    float cs = 0.f;
    #pragma unroll 8
    for (int r=0; r<64; r++) cs += sOut[r*132 + tid];
    atomicAdd(&g_m0[b*DM + tid], cs);
  }
}

// ---------------- K3: attention, 128-key tiles, deg-2 expm1, mma-l -----------
__global__ __launch_bounds__(256) void attn_bf16_kernel(){
  __shared__ __align__(1024) unsigned char sbuf[2][4096];
  int b = blockIdx.z, h = blockIdx.y;
  int tid = threadIdx.x, w = tid >> 5, lane = tid & 31;
  int gid = lane >> 2, tig = lane & 3, r7 = lane & 7;
  const float* base = g_tok + b*HW*DM + h*DH;
  int qb0 = blockIdx.x*128 + w*16;
  bool wstore = (qb0 < HW);
  int qbase = wstore ? qb0 : (HW - 16);

  uint32_t qh[4];
  #pragma unroll
  for (int i=0;i<4;i++){
    int row = qbase + gid + (i & 1)*8;
    int col = 2*tig + (i >> 1)*8;
    float2 v = *(const float2*)(base + row*DM + col);
    qh[i] = packbf(__float2bfloat16_rn(v.x*0.25f), __float2bfloat16_rn(v.y*0.25f));
  }

  float oa0E[4] = {0.f,0.f,0.f,0.f};
  float oa1E[4] = {0.f,0.f,0.f,0.f};
  float oa0O[4] = {0.f,0.f,0.f,0.f};
  float oa1O[4] = {0.f,0.f,0.f,0.f};
  float lsE[4]  = {0.f,0.f,0.f,0.f};
  float lsO[4]  = {0.f,0.f,0.f,0.f};

  const u64 CH  = pack2(0.5f, 0.5f);
  const u64 C1  = pack2(1.0f, 1.0f);
  const uint32_t ONES = 0x3F803F80u;

  uint32_t sb0 = (uint32_t)__cvta_generic_to_shared(&sbuf[0][0]);
  uint32_t aScore = sb0 + (uint32_t)((r7 + ((lane >> 4) & 1)*8)*16 + ((lane >> 3) & 1)*2048);
  uint32_t aPV    = sb0 + (uint32_t)((r7 + ((lane >> 3) & 1)*8)*16 + ((lane >> 4) & 1)*2048);

  int key0 = tid >> 2, quarter = tid & 3;
  const float* g0 = base + key0*DM + quarter*4;
  const float* g1 = g0 + 64*DM;
  uint32_t dst0 = sb0 + (uint32_t)((quarter >> 1)*2048 + key0*16 + (quarter & 1)*8);
  uint32_t dst1 = dst0 + 64*16;

  {
    float4 v0 = *(const float4*)(g0);
    float4 v1 = *(const float4*)(g1);
    sts64(dst0, cvt_bf16x2_ff(v0.x, v0.y), cvt_bf16x2_ff(v0.z, v0.w));
    sts64(dst1, cvt_bf16x2_ff(v1.x, v1.y), cvt_bf16x2_ff(v1.z, v1.w));
  }
  __syncthreads();

  for (int kb=0; kb<13; kb++){
    float4 nv0, nv1;
    if (kb < 12){
      nv0 = *(const float4*)(g0 + (kb+1)*128*DM);
      int gk1 = (kb+1)*128 + key0 + 64;
      if (gk1 < HW) nv1 = *(const float4*)(g1 + (kb+1)*128*DM);
      else          nv1 = make_float4(0.f, 0.f, 0.f, 0.f);
    }
    uint32_t bufoff = (uint32_t)((kb & 1)*4096);
    uint32_t aS = aScore + bufoff;
    uint32_t aP = aPV + bufoff;

    #pragma unroll
    for (int ck=0; ck<8; ck++){
      uint32_t off = (uint32_t)(ck*256);
      uint32_t kh[4], vv[4];
      ldsm4 (aS + off, kh);
      ldsm4t(aP + off, vv);

      float cA[4] = {0.f,0.f,0.f,0.f};
      float cB[4] = {0.f,0.f,0.f,0.f};
      mma_bf16(cA, qh, kh[0], kh[1]);
      mma_bf16(cB, qh, kh[2], kh[3]);

      u64 tA01 = pack2(cA[0], cA[1]);
      u64 tA23 = pack2(cA[2], cA[3]);
      u64 tB01 = pack2(cB[0], cB[1]);
      u64 tB23 = pack2(cB[2], cB[3]);
      u64 wA01 = fma2(tA01, CH, C1);
      u64 wA23 = fma2(tA23, CH, C1);
      u64 wB01 = fma2(tB01, CH, C1);
      u64 wB23 = fma2(tB23, CH, C1);
      u64 uA01 = mul2(tA01, wA01);
      u64 uA23 = mul2(tA23, wA23);
      u64 uB01 = mul2(tB01, wB01);
      u64 uB23 = mul2(tB23, wB23);

      uint32_t pa[4];
      pa[0] = cvt_bf16x2(uA01);
      pa[1] = cvt_bf16x2(uA23);
      pa[2] = cvt_bf16x2(uB01);
      pa[3] = cvt_bf16x2(uB23);

      if (ck & 1){
        mma_bf16(oa0O, pa, vv[0], vv[1]);
        mma_bf16(oa1O, pa, vv[2], vv[3]);
        mma_bf16(lsO,  pa, ONES,  ONES);
      } else {
        mma_bf16(oa0E, pa, vv[0], vv[1]);
        mma_bf16(oa1E, pa, vv[2], vv[3]);
        mma_bf16(lsE,  pa, ONES,  ONES);
      }
    }

    if (kb < 12){
      uint32_t d = (uint32_t)(((kb+1) & 1)*4096);
      sts64(dst0 + d, cvt_bf16x2_ff(nv0.x, nv0.y), cvt_bf16x2_ff(nv0.z, nv0.w));
      sts64(dst1 + d, cvt_bf16x2_ff(nv1.x, nv1.y), cvt_bf16x2_ff(nv1.z, nv1.w));
    }
    __syncthreads();
  }

  float oa0[4], oa1[4];
  #pragma unroll
  for (int i=0;i<4;i++){ oa0[i] = oa0E[i] + oa0O[i]; oa1[i] = oa1E[i] + oa1O[i]; }
  float inv0 = 1.0f / (1600.0f + (lsE[0] + lsO[0]));
  float inv8 = 1.0f / (1600.0f + (lsE[2] + lsO[2]));

  if (wstore){
    const float* m0p = g_m0 + b*DM + h*DH;
    float* outb = g_attn + (b*HW + qbase)*DM + h*DH;
    float* oas[2] = {oa0, oa1};
    #pragma unroll
    for (int nt=0; nt<2; nt++){
      int d0 = nt*8 + 2*tig;
      float m0a = m0p[d0], m0b = m0p[d0+1];
      outb[(gid  )*DM + d0    ] = (oas[nt][0] + m0a) * inv0;
      outb[(gid  )*DM + d0 + 1] = (oas[nt][1] + m0b) * inv0;
      outb[(gid+8)*DM + d0    ] = (oas[nt][2] + m0a) * inv8;
      outb[(gid+8)*DM + d0 + 1] = (oas[nt][3] + m0b) * inv8;
    }
  }
}

// ---------------- K4: gemm2 split-bf16 mma, 32-row tiles, preconverted W -----
__global__ __launch_bounds__(256, 3) void gemm2_mma_kernel(const float* __restrict__ b2,
                                                           float* __restrict__ img_out){
  __shared__ __align__(1024) unsigned char sA[2][8192];
  __shared__ __align__(1024) unsigned char sW[2][8192];
  int tile = blockIdx.x;
  int b = tile / 50, pbase = (tile % 50) * 32;
  int tid = threadIdx.x, w = tid >> 5, lane = tid & 31;
  int gid = lane >> 2, tig = lane & 3, r7 = lane & 7;

  uint32_t sa0 = (uint32_t)__cvta_generic_to_shared(&sA[0][0]);
  uint32_t sw0 = (uint32_t)__cvta_generic_to_shared(&sW[0][0]);

  {
    const float* Abase = g_attn + (size_t)(tile*32)*DM;
    #pragma unroll
    for (int it=0; it<4; it++){
      int idx = tid + it*256;
      int r = idx >> 5, kc4 = idx & 31;
      int kc = kc4 >> 1, half = kc4 & 1;
      float4 v = *(const float4*)(Abase + r*DM + kc4*4);
      uint32_t h0, l0, h1, l1;
      split2(v.x, v.y, h0, l0);
      split2(v.z, v.w, h1, l1);
      uint32_t addr = sa0 + (uint32_t)(r*256 + ((kc ^ (r & 7)))*16 + half*8);
      sts64(addr,        h0, h1);
      sts64(addr + 8192, l0, l1);
    }
  }

  float oa[8][4];
  #pragma unroll
  for (int i=0;i<8;i++){ oa[i][0]=0.f; oa[i][1]=0.f; oa[i][2]=0.f; oa[i][3]=0.f; }

  int arow = (w & 1)*16 + r7 + ((lane >> 3) & 1)*8;
  int klocal = r7 + ((lane >> 3) & 1)*8;
  int ncsel  = (lane >> 4) & 1;
  int nbase  = (w >> 1) * 8;

  // W stage staging: 2 units of 16B per thread per plane
  int kkS0 = tid >> 5, ncS0 = tid & 31;          // unit (kk, nc), then +8 rows
  const __nv_bfloat16* w2hp = g_w2h + kkS0*CI + ncS0*8;
  const __nv_bfloat16* w2lp = g_w2l + kkS0*CI + ncS0*8;
  uint32_t wS0 = (uint32_t)(kkS0*512 + ((ncS0 ^ (kkS0 & 7)))*16);
  uint32_t wS1 = (uint32_t)((kkS0+8)*512 + ((ncS0 ^ ((kkS0+8) & 7)))*16);

  for (int ks=0; ks<8; ks++){
    __syncthreads();
    {
      uint4 vh0 = *(const uint4*)(w2hp + (ks*16)*CI);
      uint4 vh1 = *(const uint4*)(w2hp + (ks*16 + 8)*CI);
      uint4 vl0 = *(const uint4*)(w2lp + (ks*16)*CI);
      uint4 vl1 = *(const uint4*)(w2lp + (ks*16 + 8)*CI);
      sts128a(sw0 + wS0,        vh0);
      sts128a(sw0 + wS1,        vh1);
      sts128a(sw0 + wS0 + 8192, vl0);
      sts128a(sw0 + wS1 + 8192, vl1);
    }
    __syncthreads();

    uint32_t ah[4], al[4];
    {
      int kcv = 2*ks + ((lane >> 4) & 1);
      uint32_t aaddr = sa0 + (uint32_t)(arow*256 + ((kcv ^ r7))*16);
      ldsm4(aaddr, ah);
      ldsm4(aaddr + 8192, al);
    }

    #pragma unroll
    for (int p=0; p<4; p++){
      int nc0 = nbase + 2*p;
      uint32_t waddr = sw0 + (uint32_t)(klocal*512 + (((nc0 + ncsel) ^ r7))*16);
      uint32_t wh[4], wl[4];
      ldsm4t(waddr, wh);
      ldsm4t(waddr + 8192, wl);
      mma_bf16(oa[2*p],   ah, wh[0], wh[1]);
      mma_bf16(oa[2*p],   ah, wl[0], wl[1]);
      mma_bf16(oa[2*p],   al, wh[0], wh[1]);
      mma_bf16(oa[2*p+1], ah, wh[2], wh[3]);
      mma_bf16(oa[2*p+1], ah, wl[2], wl[3]);
      mma_bf16(oa[2*p+1], al, wh[2], wh[3]);
    }
  }

  int p0 = pbase + (w & 1)*16 + gid;
  float* outB = img_out + (size_t)b*CI*HW;
  #pragma unroll
  for (int nc=0; nc<8; nc++){
    int c0 = (w >> 1)*64 + nc*8 + 2*tig;
    float bb0 = __ldg(b2 + c0), bb1 = __ldg(b2 + c0 + 1);
    float v00 = oa[nc][0] + bb0, v01 = oa[nc][1] + bb1;
    float v10 = oa[nc][2] + bb0, v11 = oa[nc][3] + bb1;
    outB[(size_t)c0*HW + p0]           = v00;
    outB[(size_t)(c0+1)*HW + p0]       = v01;
    outB[(size_t)c0*HW + p0 + 8]       = v10;
    outB[(size_t)(c0+1)*HW + p0 + 8]   = v11;
    float e00 = fmaxf(v00, 1e-6f), e01 = fmaxf(v01, 1e-6f);
    float e10 = fmaxf(v10, 1e-6f), e11 = fmaxf(v11, 1e-6f);
    float pc0 = e00*e00*e00 + e10*e10*e10;
    float pc1 = e01*e01*e01 + e11*e11*e11;
    pc0 += __shfl_xor_sync(0xffffffffu, pc0, 4);
    pc1 += __shfl_xor_sync(0xffffffffu, pc1, 4);
    pc0 += __shfl_xor_sync(0xffffffffu, pc0, 8);
    pc1 += __shfl_xor_sync(0xffffffffu, pc1, 8);
    pc0 += __shfl_xor_sync(0xffffffffu, pc0, 16);
    pc1 += __shfl_xor_sync(0xffffffffu, pc1, 16);
    if (lane < 4){
      atomicAdd(&g_imgacc[b*CI + c0],     pc0);
      atomicAdd(&g_imgacc[b*CI + c0 + 1], pc1);
    }
  }
}

// ---------------- K7: cloud l2norm + segmented clamp^3 sum -------------------
__global__ __launch_bounds__(256) void cloud_kernel(const float* __restrict__ cf,
                                                    const int* __restrict__ bids,
                                                    float* __restrict__ cloud_out){
  __shared__ float sseg[NB*DM];
  __shared__ float scnt[NB];
  int tid = threadIdx.x;
  for (int i=tid; i<NB*DM; i+=256) sseg[i] = 0.f;
  if (tid < NB) scnt[tid] = 0.f;
  __syncthreads();
  int w = tid >> 5, lane = tid & 31;
  int rbase = blockIdx.x*64 + w*8;
  #pragma unroll
  for (int i=0;i<8;i++){
    int row = rbase + i;
    int bid = bids[row];
    float4 v = *(const float4*)(cf + row*DM + lane*4);
    float sq = v.x*v.x + v.y*v.y + v.z*v.z + v.w*v.w;
    #pragma unroll
    for (int off=16; off; off>>=1) sq += __shfl_xor_sync(0xffffffffu, sq, off);
    float inv = 1.0f / fmaxf(sqrtf(sq), 1e-12f);
    float x0=v.x*inv, x1=v.y*inv, x2=v.z*inv, x3=v.w*inv;
    *(float4*)(cloud_out + row*DM + lane*4) = make_float4(x0,x1,x2,x3);
    float c0=fmaxf(x0,1e-6f), c1=fmaxf(x1,1e-6f), c2=fmaxf(x2,1e-6f), c3=fmaxf(x3,1e-6f);
    float* sp = sseg + bid*DM + lane*4;
    atomicAdd(sp+0, c0*c0*c0);
    atomicAdd(sp+1, c1*c1*c1);
    atomicAdd(sp+2, c2*c2*c2);
    atomicAdd(sp+3, c3*c3*c3);
    if (lane == 0) atomicAdd(&scnt[bid], 1.0f);
  }
  __syncthreads();
  for (int i=tid; i<NB*DM; i+=256) atomicAdd(&g_seg[i], sseg[i]);
  if (tid < NB) atomicAdd(&g_cnt[tid], scnt[tid]);
}

// ---------------- K8: finalize GeM outputs ----------------
__global__ void finalize_kernel(float* __restrict__ image_gem, float* __restrict__ cloud_gem){
  int i = blockIdx.x*256 + threadIdx.x;
  if (i < NB*CI) image_gem[i] = cbrtf(g_imgacc[i] * (1.0f/1600.0f));
  if (i < NB*DM) cloud_gem[i] = cbrtf(g_seg[i] / fmaxf(g_cnt[i>>7], 1.0f));
}

// ---------------- launch ----------------
extern "C" void kernel_launch(void* const* d_in, const int* in_sizes, int n_in,
                              void* d_out, int out_size){
  const float* img  = (const float*)d_in[0];
  const float* cf   = (const float*)d_in[1];
  const int*   bids = (const int*)  d_in[2];
  const float* W1   = (const float*)d_in[3];
  const float* b1   = (const float*)d_in[4];
  const float* W2   = (const float*)d_in[5];
  const float* b2   = (const float*)d_in[6];

  float* out       = (float*)d_out;
  float* img_out   = out;                                  // 8*256*1600
  float* cloud_out = out + (size_t)NB*CI*HW;               // 32768*128
  float* image_gem = cloud_out + (size_t)NCLOUD*DM;        // 2048
  float* cloud_gem = image_gem + NB*CI;                    // 1024

  zero_kernel<<<8, 256>>>();
  prep_w_kernel<<<128, 256>>>(W1, W2);
  gemm1_mma_kernel<<<200, 256>>>(img, b1);
  attn_bf16_kernel<<<dim3(13, NHEAD, NB), 256>>>();
  gemm2_mma_kernel<<<400, 256>>>(b2, img_out);
  cloud_kernel<<<512, 256>>>(cf, bids, cloud_out);
  finalize_kernel<<<8, 256>>>(image_gem, cloud_gem);
}